// round 16
// baseline (speedup 1.0000x reference)
#include <cuda_runtime.h>
#include <cuda_fp16.h>
#include <mma.h>
#include <type_traits>

using namespace nvcuda;

// Problem constants
#define N_NODES 50000
#define N_EDGES 1600000
#define E_TOT   (N_EDGES + N_NODES)
#define FDIM    128
#define NHEAD   2
#define NEG_SLOPE 0.2f

#define LDA 136   // halves; 272B row stride
#define LDC 132   // floats
#define GEMM_SMEM (2 * 128 * LDA * (int)sizeof(__half))   // 69632 B

// ---------------- device scratch ----------------
__device__ int g_is64;
__device__ int g_counts[N_NODES];
__device__ int g_rowptr[N_NODES + 1];
__device__ int g_fill[N_NODES];
__device__ __align__(16) int g_col[E_TOT + 8];   // +8 pad for masked tail
__device__ __align__(16) __half g_h16[(size_t)N_NODES * FDIM];   // GEMM out / agg gather
__device__ __align__(16) __half g_x16[(size_t)N_NODES * FDIM];   // inter-layer activations
__device__ __align__(16) float  g_esrc[N_NODES * NHEAD];   // [n][2] -> float2
__device__ __align__(16) float  g_edst[N_NODES * NHEAD];

// ---------------- CSR build (direct reads of edge_index) ----------------
__global__ void k_init_detect(const long long* ei) {
    int i = blockIdx.x * blockDim.x + threadIdx.x;
    if (i < N_NODES) g_counts[i] = 1;   // self loop
    if (i == 0) {
        int ok = 1;
        for (int t = 0; t < 16; t++) {
            long long v = ei[t];
            if (v < 0 || v >= (long long)N_NODES) { ok = 0; break; }
        }
        g_is64 = ok;
    }
}

__global__ void k_hist(const void* eiv) {
    int e = blockIdx.x * blockDim.x + threadIdx.x;
    if (e >= N_EDGES) return;
    int d;
    if (g_is64) d = (int)((const long long*)eiv)[N_EDGES + e];
    else        d = ((const int*)eiv)[N_EDGES + e];
    atomicAdd(&g_counts[d], 1);
}

// single-block exclusive scan over g_counts + self-loop + fill init
__global__ void k_scan_all() {
    __shared__ int totals[1024];
    const int t = threadIdx.x;
    const int PER = (N_NODES + 1023) / 1024;   // 49
    const int base = t * PER;

    int run = 0;
#pragma unroll 4
    for (int j = 0; j < PER; j++) {
        int i = base + j;
        if (i < N_NODES) {
            int c = g_counts[i];
            g_rowptr[i] = run;      // local exclusive
            run += c;
        }
    }
    totals[t] = run;
    __syncthreads();
    for (int o = 1; o < 1024; o <<= 1) {
        int v = (t >= o) ? totals[t - o] : 0;
        __syncthreads();
        totals[t] += v;
        __syncthreads();
    }
    int toff = (t == 0) ? 0 : totals[t - 1];
#pragma unroll 4
    for (int j = 0; j < PER; j++) {
        int i = base + j;
        if (i < N_NODES) {
            int rp = g_rowptr[i] + toff;
            g_rowptr[i] = rp;
            g_col[rp] = i;          // self loop in slot 0
            g_fill[i] = 1;
        }
    }
    if (t == 0) g_rowptr[N_NODES] = E_TOT;
}

__global__ void k_scatter(const void* eiv) {
    int e = blockIdx.x * blockDim.x + threadIdx.x;
    if (e >= N_EDGES) return;
    int s, d;
    if (g_is64) {
        const long long* p = (const long long*)eiv;
        s = (int)p[e];
        d = (int)p[N_EDGES + e];
    } else {
        const int* p = (const int*)eiv;
        s = p[e];
        d = p[N_EDGES + e];
    }
    int pos = g_rowptr[d] + atomicAdd(&g_fill[d], 1);
    g_col[pos] = s;
}

// ---------------- HMMA GEMM (wmma, templated A dtype) + fused logits --------
extern __shared__ char dynsmem[];

template <typename AT>
__global__ void k_gemm_wmma_fused(
    const AT* __restrict__ A, const float* __restrict__ B,
    __half* __restrict__ C16,
    const float* __restrict__ a_src, const float* __restrict__ a_dst, int M) {
    __half* As = (__half*)dynsmem;          // 128 x LDA
    __half* Bs = As + 128 * LDA;            // 128 x LDA
    float*  Cs = (float*)dynsmem;           // reused for epilogue, 128 x LDC

    const int tid  = threadIdx.x;
    const int wid  = tid >> 5;
    const int row0 = blockIdx.x * 128;

    // ---- stage B (fp32 W -> fp16) ----
#pragma unroll
    for (int i = 0; i < 16; i++) {
        int lin = tid + i * 256;
        int row = lin >> 5;
        int col = (lin & 31) * 4;
        float4 w = *(const float4*)&B[lin * 4];
        __half2 b01 = __floats2half2_rn(w.x, w.y);
        __half2 b23 = __floats2half2_rn(w.z, w.w);
        uint2 pb;
        pb.x = *(unsigned*)&b01; pb.y = *(unsigned*)&b23;
        *(uint2*)&Bs[row * LDA + col] = pb;
    }

    // ---- stage A ----
    if constexpr (std::is_same_v<AT, float>) {
#pragma unroll
        for (int i = 0; i < 16; i++) {
            int lin = tid + i * 256;
            int row = lin >> 5;
            int col = (lin & 31) * 4;
            float4 v = make_float4(0.f, 0.f, 0.f, 0.f);
            if (row0 + row < M) v = *(const float4*)&A[(size_t)(row0 + row) * 128 + col];
            __half2 a01 = __floats2half2_rn(v.x, v.y);
            __half2 a23 = __floats2half2_rn(v.z, v.w);
            uint2 pa;
            pa.x = *(unsigned*)&a01; pa.y = *(unsigned*)&a23;
            *(uint2*)&As[row * LDA + col] = pa;
        }
    } else {
#pragma unroll
        for (int i = 0; i < 8; i++) {
            int lin = tid + i * 256;        // uint4 = 8 halves
            int row = lin >> 4;
            int col = (lin & 15) * 8;
            uint4 v = make_uint4(0u, 0u, 0u, 0u);
            if (row0 + row < M) v = *(const uint4*)&A[(size_t)(row0 + row) * 128 + col];
            *(uint4*)&As[row * LDA + col] = v;
        }
    }
    __syncthreads();

    const int wm = wid & 3;
    const int wn = wid >> 2;

    wmma::fragment<wmma::accumulator, 16, 16, 16, float> acc[2][4];
#pragma unroll
    for (int a = 0; a < 2; a++)
#pragma unroll
        for (int b = 0; b < 4; b++) wmma::fill_fragment(acc[a][b], 0.f);

#pragma unroll
    for (int kk = 0; kk < 128; kk += 16) {
        wmma::fragment<wmma::matrix_a, 16, 16, 16, __half, wmma::row_major> af[2];
        wmma::fragment<wmma::matrix_b, 16, 16, 16, __half, wmma::row_major> bf[4];
#pragma unroll
        for (int a = 0; a < 2; a++)
            wmma::load_matrix_sync(af[a], &As[(wm * 32 + a * 16) * LDA + kk], LDA);
#pragma unroll
        for (int b = 0; b < 4; b++)
            wmma::load_matrix_sync(bf[b], &Bs[kk * LDA + wn * 64 + b * 16], LDA);
#pragma unroll
        for (int a = 0; a < 2; a++)
#pragma unroll
            for (int b = 0; b < 4; b++)
                wmma::mma_sync(acc[a][b], af[a], bf[b], acc[a][b]);
    }
    __syncthreads();

#pragma unroll
    for (int a = 0; a < 2; a++)
#pragma unroll
        for (int b = 0; b < 4; b++)
            wmma::store_matrix_sync(&Cs[(wm * 32 + a * 16) * LDC + wn * 64 + b * 16],
                                    acc[a][b], LDC, wmma::mem_row_major);
    __syncthreads();

    const int tr = tid >> 4;
    const int tc = tid & 15;

    float4 as0 = *(const float4*)&a_src[tc * 8];
    float4 as1 = *(const float4*)&a_src[tc * 8 + 4];
    float4 ad0 = *(const float4*)&a_dst[tc * 8];
    float4 ad1 = *(const float4*)&a_dst[tc * 8 + 4];

#pragma unroll
    for (int i = 0; i < 8; i++) {
        int srow = tr * 8 + i;
        float4 cA = *(const float4*)&Cs[srow * LDC + tc * 8];
        float4 cB = *(const float4*)&Cs[srow * LDC + tc * 8 + 4];
        float c0 = cA.x, c1 = cA.y, c2 = cA.z, c3 = cA.w;
        float c4 = cB.x, c5 = cB.y, c6 = cB.z, c7 = cB.w;

        int row = row0 + srow;
        if (row < M) {
            __half2 p01 = __floats2half2_rn(c0, c1);
            __half2 p23 = __floats2half2_rn(c2, c3);
            __half2 p45 = __floats2half2_rn(c4, c5);
            __half2 p67 = __floats2half2_rn(c6, c7);
            uint4 pk;
            pk.x = *(unsigned*)&p01; pk.y = *(unsigned*)&p23;
            pk.z = *(unsigned*)&p45; pk.w = *(unsigned*)&p67;
            *(uint4*)&C16[(size_t)row * 128 + tc * 8] = pk;
        }

        float ds = c0 * as0.x + c1 * as0.y + c2 * as0.z + c3 * as0.w
                 + c4 * as1.x + c5 * as1.y + c6 * as1.z + c7 * as1.w;
        float dd = c0 * ad0.x + c1 * ad0.y + c2 * ad0.z + c3 * ad0.w
                 + c4 * ad1.x + c5 * ad1.y + c6 * ad1.z + c7 * ad1.w;
#pragma unroll
        for (int o = 4; o > 0; o >>= 1) {
            ds += __shfl_down_sync(0xffffffffu, ds, o, 8);
            dd += __shfl_down_sync(0xffffffffu, dd, o, 8);
        }
        if (row < M && (tc & 7) == 0) {
            int head = tc >> 3;
            g_esrc[row * 2 + head] = ds;
            g_edst[row * 2 + head] = dd;
        }
    }
}

// ---------------- edge aggregation (templated output dtype) ------------------
template <typename OT>
__global__ __launch_bounds__(256) void k_agg(const float* __restrict__ bias,
                                             OT* __restrict__ out, int do_relu) {
    int warp = (blockIdx.x * blockDim.x + threadIdx.x) >> 5;
    int lane = threadIdx.x & 31;
    if (warp >= N_NODES) return;

    const int d    = warp;
    const int head = lane >> 4;
    const float ed = __ldg(&g_edst[d * 2 + head]);
    const int beg  = __ldg(&g_rowptr[d]);
    const int end  = __ldg(&g_rowptr[d + 1]);

    const uint2* __restrict__ h2 = (const uint2*)g_h16;
    const int* __restrict__ col = g_col;
    const float2* __restrict__ esrc2 = (const float2*)g_esrc;

    float s = 0.f;
    float4 acc = make_float4(0.f, 0.f, 0.f, 0.f);

    int e = beg;
#pragma unroll 1
    for (; e < end && (e & 3); e++) {
        int c0 = __ldg(&col[e]);
        float2 es2 = __ldg(&esrc2[c0]);
        float es0 = head ? es2.y : es2.x;
        uint2 r0 = __ldg(&h2[(size_t)c0 * 32 + lane]);
        float x0 = es0 + ed;
        float lv0 = fminf(x0 > 0.f ? x0 : NEG_SLOPE * x0, 80.f);
        float p0 = __expf(lv0);
        float2 f0a = __half22float2(*(__half2*)&r0.x);
        float2 f0b = __half22float2(*(__half2*)&r0.y);
        s += p0;
        acc.x += p0 * f0a.x;
        acc.y += p0 * f0a.y;
        acc.z += p0 * f0b.x;
        acc.w += p0 * f0b.y;
    }

#pragma unroll 1
    for (; e + 8 <= end; e += 8) {
        int4 ca = __ldg((const int4*)&col[e]);
        int4 cb = __ldg((const int4*)&col[e + 4]);
        int cs[8] = {ca.x, ca.y, ca.z, ca.w, cb.x, cb.y, cb.z, cb.w};

        int myc = cs[lane & 7];
        float2 es2 = __ldg(&esrc2[myc]);
        float es = (lane >= 16) ? es2.y : es2.x;

        uint2 r[8];
#pragma unroll
        for (int j = 0; j < 8; j++)
            r[j] = __ldg(&h2[(size_t)cs[j] * 32 + lane]);

        float x  = es + ed;
        float lv = fminf(x > 0.f ? x : NEG_SLOPE * x, 80.f);
        float myp = __expf(lv);

#pragma unroll
        for (int j = 0; j < 8; j++) {
            float pj = __shfl_sync(0xffffffffu, myp, j, 16);
            float2 fa = __half22float2(*(__half2*)&r[j].x);
            float2 fb = __half22float2(*(__half2*)&r[j].y);
            s += pj;
            acc.x += pj * fa.x;
            acc.y += pj * fa.y;
            acc.z += pj * fb.x;
            acc.w += pj * fb.y;
        }
    }

    if (e < end) {
        int rem = end - e;
        int4 ta = __ldg((const int4*)&col[e]);
        int4 tb = __ldg((const int4*)&col[e + 4]);
        int cs[8] = {ta.x, ta.y, ta.z, ta.w, tb.x, tb.y, tb.z, tb.w};
        int c0v = cs[0];
#pragma unroll
        for (int j = 0; j < 8; j++) cs[j] = (j < rem) ? cs[j] : c0v;

        int myc = cs[lane & 7];
        float2 es2 = __ldg(&esrc2[myc]);
        float es = (lane >= 16) ? es2.y : es2.x;

        uint2 r[8];
#pragma unroll
        for (int j = 0; j < 8; j++)
            r[j] = __ldg(&h2[(size_t)cs[j] * 32 + lane]);

        float x  = es + ed;
        float lv = fminf(x > 0.f ? x : NEG_SLOPE * x, 80.f);
        float myp = ((lane & 7) < rem) ? __expf(lv) : 0.f;

#pragma unroll
        for (int j = 0; j < 8; j++) {
            float pj = __shfl_sync(0xffffffffu, myp, j, 16);
            float2 fa = __half22float2(*(__half2*)&r[j].x);
            float2 fb = __half22float2(*(__half2*)&r[j].y);
            s += pj;
            acc.x += pj * fa.x;
            acc.y += pj * fa.y;
            acc.z += pj * fb.x;
            acc.w += pj * fb.y;
        }
    }

    float inv = 1.f / (s + 1e-16f);
    float4 bv = __ldg(&((const float4*)bias)[lane]);
    float4 o;
    o.x = acc.x * inv + bv.x;
    o.y = acc.y * inv + bv.y;
    o.z = acc.z * inv + bv.z;
    o.w = acc.w * inv + bv.w;
    if (do_relu) {
        o.x = fmaxf(o.x, 0.f); o.y = fmaxf(o.y, 0.f);
        o.z = fmaxf(o.z, 0.f); o.w = fmaxf(o.w, 0.f);
    }
    if constexpr (std::is_same_v<OT, float>) {
        ((float4*)out)[(size_t)d * 32 + lane] = o;
    } else {
        __half2 h01 = __floats2half2_rn(o.x, o.y);
        __half2 h23 = __floats2half2_rn(o.z, o.w);
        uint2 pk;
        pk.x = *(unsigned*)&h01; pk.y = *(unsigned*)&h23;
        ((uint2*)out)[(size_t)d * 32 + lane] = pk;
    }
}

// ---------------- host side ----------------
static cudaStream_t s_csr = nullptr;
static cudaEvent_t  ev_fork = nullptr, ev_join = nullptr;

extern "C" void kernel_launch(void* const* d_in, const int* in_sizes, int n_in,
                              void* d_out, int out_size) {
    const float* x      = (const float*)d_in[0];
    const void*  ei     = d_in[1];
    const float* W_in   = (const float*)d_in[2];
    const float* as_in  = (const float*)d_in[3];
    const float* ad_in  = (const float*)d_in[4];
    const float* b_in   = (const float*)d_in[5];
    const float* W_h    = (const float*)d_in[6];
    const float* as_h   = (const float*)d_in[7];
    const float* ad_h   = (const float*)d_in[8];
    const float* b_h    = (const float*)d_in[9];
    const float* W_out  = (const float*)d_in[10];
    const float* as_out = (const float*)d_in[11];
    const float* ad_out = (const float*)d_in[12];
    const float* b_out  = (const float*)d_in[13];
    float* out = (float*)d_out;

    __half* p_h16 = nullptr;
    __half* p_x16 = nullptr;
    cudaGetSymbolAddress((void**)&p_h16, g_h16);
    cudaGetSymbolAddress((void**)&p_x16, g_x16);

    if (!s_csr) {
        cudaStreamCreate(&s_csr);
        cudaEventCreateWithFlags(&ev_fork, cudaEventDisableTiming);
        cudaEventCreateWithFlags(&ev_join, cudaEventDisableTiming);
        cudaFuncSetAttribute(k_gemm_wmma_fused<float>,
                             cudaFuncAttributeMaxDynamicSharedMemorySize, GEMM_SMEM);
        cudaFuncSetAttribute(k_gemm_wmma_fused<__half>,
                             cudaFuncAttributeMaxDynamicSharedMemorySize, GEMM_SMEM);
    }

    const int eb = (N_EDGES + 255) / 256;
    const int nb = (N_NODES + 255) / 256;
    const int gemm_blocks = (N_NODES + 127) / 128;
    const int warp_blocks = (N_NODES * 32 + 255) / 256;

    // ---- fork: CSR build on side stream, layer-0 GEMM in parallel ----
    cudaEventRecord(ev_fork, 0);
    cudaStreamWaitEvent(s_csr, ev_fork, 0);
    k_init_detect<<<nb, 256, 0, s_csr>>>((const long long*)ei);
    k_hist<<<eb, 256, 0, s_csr>>>(ei);
    k_scan_all<<<1, 1024, 0, s_csr>>>();
    k_scatter<<<eb, 256, 0, s_csr>>>(ei);
    cudaEventRecord(ev_join, s_csr);

    k_gemm_wmma_fused<float><<<gemm_blocks, 256, GEMM_SMEM>>>(
        x, W_in, p_h16, as_in, ad_in, N_NODES);

    cudaStreamWaitEvent(0, ev_join, 0);
    k_agg<__half><<<warp_blocks, 256>>>(b_in, p_x16, 1);

    k_gemm_wmma_fused<__half><<<gemm_blocks, 256, GEMM_SMEM>>>(
        p_x16, W_h, p_h16, as_h, ad_h, N_NODES);
    k_agg<__half><<<warp_blocks, 256>>>(b_h, p_x16, 1);

    k_gemm_wmma_fused<__half><<<gemm_blocks, 256, GEMM_SMEM>>>(
        p_x16, W_h + 128 * 128, p_h16, as_h + 128, ad_h + 128, N_NODES);
    k_agg<__half><<<warp_blocks, 256>>>(b_h + 128, p_x16, 1);

    k_gemm_wmma_fused<__half><<<gemm_blocks, 256, GEMM_SMEM>>>(
        p_x16, W_out, p_h16, as_out, ad_out, N_NODES);
    k_agg<float><<<warp_blocks, 256>>>(b_out, out, 0);
}

// round 17
// speedup vs baseline: 1.5006x; 1.5006x over previous
#include <cuda_runtime.h>
#include <cuda_fp16.h>
#include <mma.h>
#include <type_traits>

using namespace nvcuda;

// Problem constants
#define N_NODES 50000
#define N_EDGES 1600000
#define E_TOT   (N_EDGES + N_NODES)
#define FDIM    128
#define NHEAD   2
#define NEG_SLOPE 0.2f

#define SCAN_BLK 1024
#define SCAN_NBLK ((N_NODES + SCAN_BLK - 1) / SCAN_BLK)   // 49

#define LDA 136   // halves; 272B row stride
#define LDC 132   // floats
#define GEMM_SMEM (2 * 128 * LDA * (int)sizeof(__half))   // 69632 B

// ---------------- device scratch ----------------
__device__ int g_is64;
__device__ int g_counts[N_NODES];
__device__ int g_rowptr[N_NODES + 1];
__device__ int g_fill[N_NODES];
__device__ int g_partials[64];
__device__ __align__(16) int g_col[E_TOT + 8];   // +8 pad for masked tail
__device__ __align__(16) __half g_h16[(size_t)N_NODES * FDIM];   // GEMM out / agg gather
__device__ __align__(16) __half g_x16[(size_t)N_NODES * FDIM];   // inter-layer activations
__device__ __align__(16) float  g_esrc[N_NODES * NHEAD];   // [n][2] -> float2
__device__ __align__(16) float  g_edst[N_NODES * NHEAD];

// ---------------- CSR build (direct reads of edge_index, 2 edges/thread) ----
__global__ void k_init_detect(const long long* ei) {
    int i = blockIdx.x * blockDim.x + threadIdx.x;
    if (i < N_NODES) g_counts[i] = 1;   // self loop
    if (i == 0) {
        int ok = 1;
        for (int t = 0; t < 16; t++) {
            long long v = ei[t];
            if (v < 0 || v >= (long long)N_NODES) { ok = 0; break; }
        }
        g_is64 = ok;
    }
}

// N_EDGES is even: each thread handles exactly 2 edges.
__global__ void k_hist(const void* eiv) {
    int e2 = blockIdx.x * blockDim.x + threadIdx.x;
    if (e2 * 2 >= N_EDGES) return;
    int d0, d1;
    if (g_is64) {
        const longlong2* pd = (const longlong2*)((const long long*)eiv + N_EDGES);
        longlong2 v = pd[e2];
        d0 = (int)v.x; d1 = (int)v.y;
    } else {
        const int2* pd = (const int2*)((const int*)eiv + N_EDGES);
        int2 v = pd[e2];
        d0 = v.x; d1 = v.y;
    }
    atomicAdd(&g_counts[d0], 1);
    atomicAdd(&g_counts[d1], 1);
}

__global__ void k_scan1() {
    __shared__ int sh[SCAN_BLK];
    int i = blockIdx.x * SCAN_BLK + threadIdx.x;
    int v = (i < N_NODES) ? g_counts[i] : 0;
    sh[threadIdx.x] = v;
    __syncthreads();
    for (int o = 1; o < SCAN_BLK; o <<= 1) {
        int t = 0;
        if ((int)threadIdx.x >= o) t = sh[threadIdx.x - o];
        __syncthreads();
        sh[threadIdx.x] += t;
        __syncthreads();
    }
    if (i < N_NODES) g_rowptr[i] = sh[threadIdx.x] - v;
    if (threadIdx.x == SCAN_BLK - 1) g_partials[blockIdx.x] = sh[SCAN_BLK - 1];
}

__global__ void k_scan3_selfloop() {
    __shared__ int sh[64];
    if (threadIdx.x < 64)
        sh[threadIdx.x] = ((int)threadIdx.x < SCAN_NBLK) ? g_partials[threadIdx.x] : 0;
    __syncthreads();
    for (int o = 1; o < 64; o <<= 1) {
        int t = 0;
        if (threadIdx.x < 64 && (int)threadIdx.x >= o) t = sh[threadIdx.x - o];
        __syncthreads();
        if (threadIdx.x < 64) sh[threadIdx.x] += t;
        __syncthreads();
    }
    int blockOff = (blockIdx.x == 0) ? 0 : sh[blockIdx.x - 1];
    int i = blockIdx.x * SCAN_BLK + threadIdx.x;
    if (i < N_NODES) {
        int rp = g_rowptr[i] + blockOff;
        g_rowptr[i] = rp;
        g_col[rp] = i;      // self loop in slot 0
        g_fill[i] = 1;
    }
    if (i == 0) g_rowptr[N_NODES] = E_TOT;
}

__global__ void k_scatter(const void* eiv) {
    int e2 = blockIdx.x * blockDim.x + threadIdx.x;
    if (e2 * 2 >= N_EDGES) return;
    int s0, s1, d0, d1;
    if (g_is64) {
        const longlong2* ps = (const longlong2*)eiv;
        const longlong2* pd = (const longlong2*)((const long long*)eiv + N_EDGES);
        longlong2 vs = ps[e2];
        longlong2 vd = pd[e2];
        s0 = (int)vs.x; s1 = (int)vs.y;
        d0 = (int)vd.x; d1 = (int)vd.y;
    } else {
        const int2* ps = (const int2*)eiv;
        const int2* pd = (const int2*)((const int*)eiv + N_EDGES);
        int2 vs = ps[e2];
        int2 vd = pd[e2];
        s0 = vs.x; s1 = vs.y;
        d0 = vd.x; d1 = vd.y;
    }
    int p0 = g_rowptr[d0] + atomicAdd(&g_fill[d0], 1);
    g_col[p0] = s0;
    int p1 = g_rowptr[d1] + atomicAdd(&g_fill[d1], 1);
    g_col[p1] = s1;
}

// ---------------- HMMA GEMM (wmma, templated A dtype) + fused logits --------
extern __shared__ char dynsmem[];

template <typename AT>
__global__ void k_gemm_wmma_fused(
    const AT* __restrict__ A, const float* __restrict__ B,
    __half* __restrict__ C16,
    const float* __restrict__ a_src, const float* __restrict__ a_dst, int M) {
    __half* As = (__half*)dynsmem;          // 128 x LDA
    __half* Bs = As + 128 * LDA;            // 128 x LDA
    float*  Cs = (float*)dynsmem;           // reused for epilogue, 128 x LDC

    const int tid  = threadIdx.x;
    const int wid  = tid >> 5;
    const int row0 = blockIdx.x * 128;

    // ---- stage B (fp32 W -> fp16) ----
#pragma unroll
    for (int i = 0; i < 16; i++) {
        int lin = tid + i * 256;
        int row = lin >> 5;
        int col = (lin & 31) * 4;
        float4 w = *(const float4*)&B[lin * 4];
        __half2 b01 = __floats2half2_rn(w.x, w.y);
        __half2 b23 = __floats2half2_rn(w.z, w.w);
        uint2 pb;
        pb.x = *(unsigned*)&b01; pb.y = *(unsigned*)&b23;
        *(uint2*)&Bs[row * LDA + col] = pb;
    }

    // ---- stage A ----
    if constexpr (std::is_same_v<AT, float>) {
#pragma unroll
        for (int i = 0; i < 16; i++) {
            int lin = tid + i * 256;
            int row = lin >> 5;
            int col = (lin & 31) * 4;
            float4 v = make_float4(0.f, 0.f, 0.f, 0.f);
            if (row0 + row < M) v = *(const float4*)&A[(size_t)(row0 + row) * 128 + col];
            __half2 a01 = __floats2half2_rn(v.x, v.y);
            __half2 a23 = __floats2half2_rn(v.z, v.w);
            uint2 pa;
            pa.x = *(unsigned*)&a01; pa.y = *(unsigned*)&a23;
            *(uint2*)&As[row * LDA + col] = pa;
        }
    } else {
#pragma unroll
        for (int i = 0; i < 8; i++) {
            int lin = tid + i * 256;        // uint4 = 8 halves
            int row = lin >> 4;
            int col = (lin & 15) * 8;
            uint4 v = make_uint4(0u, 0u, 0u, 0u);
            if (row0 + row < M) v = *(const uint4*)&A[(size_t)(row0 + row) * 128 + col];
            *(uint4*)&As[row * LDA + col] = v;
        }
    }
    __syncthreads();

    const int wm = wid & 3;
    const int wn = wid >> 2;

    wmma::fragment<wmma::accumulator, 16, 16, 16, float> acc[2][4];
#pragma unroll
    for (int a = 0; a < 2; a++)
#pragma unroll
        for (int b = 0; b < 4; b++) wmma::fill_fragment(acc[a][b], 0.f);

#pragma unroll
    for (int kk = 0; kk < 128; kk += 16) {
        wmma::fragment<wmma::matrix_a, 16, 16, 16, __half, wmma::row_major> af[2];
        wmma::fragment<wmma::matrix_b, 16, 16, 16, __half, wmma::row_major> bf[4];
#pragma unroll
        for (int a = 0; a < 2; a++)
            wmma::load_matrix_sync(af[a], &As[(wm * 32 + a * 16) * LDA + kk], LDA);
#pragma unroll
        for (int b = 0; b < 4; b++)
            wmma::load_matrix_sync(bf[b], &Bs[kk * LDA + wn * 64 + b * 16], LDA);
#pragma unroll
        for (int a = 0; a < 2; a++)
#pragma unroll
            for (int b = 0; b < 4; b++)
                wmma::mma_sync(acc[a][b], af[a], bf[b], acc[a][b]);
    }
    __syncthreads();

#pragma unroll
    for (int a = 0; a < 2; a++)
#pragma unroll
        for (int b = 0; b < 4; b++)
            wmma::store_matrix_sync(&Cs[(wm * 32 + a * 16) * LDC + wn * 64 + b * 16],
                                    acc[a][b], LDC, wmma::mem_row_major);
    __syncthreads();

    const int tr = tid >> 4;
    const int tc = tid & 15;

    float4 as0 = *(const float4*)&a_src[tc * 8];
    float4 as1 = *(const float4*)&a_src[tc * 8 + 4];
    float4 ad0 = *(const float4*)&a_dst[tc * 8];
    float4 ad1 = *(const float4*)&a_dst[tc * 8 + 4];

#pragma unroll
    for (int i = 0; i < 8; i++) {
        int srow = tr * 8 + i;
        float4 cA = *(const float4*)&Cs[srow * LDC + tc * 8];
        float4 cB = *(const float4*)&Cs[srow * LDC + tc * 8 + 4];
        float c0 = cA.x, c1 = cA.y, c2 = cA.z, c3 = cA.w;
        float c4 = cB.x, c5 = cB.y, c6 = cB.z, c7 = cB.w;

        int row = row0 + srow;
        if (row < M) {
            __half2 p01 = __floats2half2_rn(c0, c1);
            __half2 p23 = __floats2half2_rn(c2, c3);
            __half2 p45 = __floats2half2_rn(c4, c5);
            __half2 p67 = __floats2half2_rn(c6, c7);
            uint4 pk;
            pk.x = *(unsigned*)&p01; pk.y = *(unsigned*)&p23;
            pk.z = *(unsigned*)&p45; pk.w = *(unsigned*)&p67;
            *(uint4*)&C16[(size_t)row * 128 + tc * 8] = pk;
        }

        float ds = c0 * as0.x + c1 * as0.y + c2 * as0.z + c3 * as0.w
                 + c4 * as1.x + c5 * as1.y + c6 * as1.z + c7 * as1.w;
        float dd = c0 * ad0.x + c1 * ad0.y + c2 * ad0.z + c3 * ad0.w
                 + c4 * ad1.x + c5 * ad1.y + c6 * ad1.z + c7 * ad1.w;
#pragma unroll
        for (int o = 4; o > 0; o >>= 1) {
            ds += __shfl_down_sync(0xffffffffu, ds, o, 8);
            dd += __shfl_down_sync(0xffffffffu, dd, o, 8);
        }
        if (row < M && (tc & 7) == 0) {
            int head = tc >> 3;
            g_esrc[row * 2 + head] = ds;
            g_edst[row * 2 + head] = dd;
        }
    }
}

// ---------------- edge aggregation (templated output dtype) ------------------
template <typename OT>
__global__ __launch_bounds__(256) void k_agg(const float* __restrict__ bias,
                                             OT* __restrict__ out, int do_relu) {
    int warp = (blockIdx.x * blockDim.x + threadIdx.x) >> 5;
    int lane = threadIdx.x & 31;
    if (warp >= N_NODES) return;

    const int d    = warp;
    const int head = lane >> 4;
    const float ed = __ldg(&g_edst[d * 2 + head]);
    const int beg  = __ldg(&g_rowptr[d]);
    const int end  = __ldg(&g_rowptr[d + 1]);

    const uint2* __restrict__ h2 = (const uint2*)g_h16;
    const int* __restrict__ col = g_col;
    const float2* __restrict__ esrc2 = (const float2*)g_esrc;

    float s = 0.f;
    float4 acc = make_float4(0.f, 0.f, 0.f, 0.f);

    int e = beg;
#pragma unroll 1
    for (; e < end && (e & 3); e++) {
        int c0 = __ldg(&col[e]);
        float2 es2 = __ldg(&esrc2[c0]);
        float es0 = head ? es2.y : es2.x;
        uint2 r0 = __ldg(&h2[(size_t)c0 * 32 + lane]);
        float x0 = es0 + ed;
        float lv0 = fminf(x0 > 0.f ? x0 : NEG_SLOPE * x0, 80.f);
        float p0 = __expf(lv0);
        float2 f0a = __half22float2(*(__half2*)&r0.x);
        float2 f0b = __half22float2(*(__half2*)&r0.y);
        s += p0;
        acc.x += p0 * f0a.x;
        acc.y += p0 * f0a.y;
        acc.z += p0 * f0b.x;
        acc.w += p0 * f0b.y;
    }

#pragma unroll 1
    for (; e + 8 <= end; e += 8) {
        int4 ca = __ldg((const int4*)&col[e]);
        int4 cb = __ldg((const int4*)&col[e + 4]);
        int cs[8] = {ca.x, ca.y, ca.z, ca.w, cb.x, cb.y, cb.z, cb.w};

        int myc = cs[lane & 7];
        float2 es2 = __ldg(&esrc2[myc]);
        float es = (lane >= 16) ? es2.y : es2.x;

        uint2 r[8];
#pragma unroll
        for (int j = 0; j < 8; j++)
            r[j] = __ldg(&h2[(size_t)cs[j] * 32 + lane]);

        float x  = es + ed;
        float lv = fminf(x > 0.f ? x : NEG_SLOPE * x, 80.f);
        float myp = __expf(lv);

#pragma unroll
        for (int j = 0; j < 8; j++) {
            float pj = __shfl_sync(0xffffffffu, myp, j, 16);
            float2 fa = __half22float2(*(__half2*)&r[j].x);
            float2 fb = __half22float2(*(__half2*)&r[j].y);
            s += pj;
            acc.x += pj * fa.x;
            acc.y += pj * fa.y;
            acc.z += pj * fb.x;
            acc.w += pj * fb.y;
        }
    }

    if (e < end) {
        int rem = end - e;
        int4 ta = __ldg((const int4*)&col[e]);
        int4 tb = __ldg((const int4*)&col[e + 4]);
        int cs[8] = {ta.x, ta.y, ta.z, ta.w, tb.x, tb.y, tb.z, tb.w};
        int c0v = cs[0];
#pragma unroll
        for (int j = 0; j < 8; j++) cs[j] = (j < rem) ? cs[j] : c0v;

        int myc = cs[lane & 7];
        float2 es2 = __ldg(&esrc2[myc]);
        float es = (lane >= 16) ? es2.y : es2.x;

        uint2 r[8];
#pragma unroll
        for (int j = 0; j < 8; j++)
            r[j] = __ldg(&h2[(size_t)cs[j] * 32 + lane]);

        float x  = es + ed;
        float lv = fminf(x > 0.f ? x : NEG_SLOPE * x, 80.f);
        float myp = ((lane & 7) < rem) ? __expf(lv) : 0.f;

#pragma unroll
        for (int j = 0; j < 8; j++) {
            float pj = __shfl_sync(0xffffffffu, myp, j, 16);
            float2 fa = __half22float2(*(__half2*)&r[j].x);
            float2 fb = __half22float2(*(__half2*)&r[j].y);
            s += pj;
            acc.x += pj * fa.x;
            acc.y += pj * fa.y;
            acc.z += pj * fb.x;
            acc.w += pj * fb.y;
        }
    }

    float inv = 1.f / (s + 1e-16f);
    float4 bv = __ldg(&((const float4*)bias)[lane]);
    float4 o;
    o.x = acc.x * inv + bv.x;
    o.y = acc.y * inv + bv.y;
    o.z = acc.z * inv + bv.z;
    o.w = acc.w * inv + bv.w;
    if (do_relu) {
        o.x = fmaxf(o.x, 0.f); o.y = fmaxf(o.y, 0.f);
        o.z = fmaxf(o.z, 0.f); o.w = fmaxf(o.w, 0.f);
    }
    if constexpr (std::is_same_v<OT, float>) {
        ((float4*)out)[(size_t)d * 32 + lane] = o;
    } else {
        __half2 h01 = __floats2half2_rn(o.x, o.y);
        __half2 h23 = __floats2half2_rn(o.z, o.w);
        uint2 pk;
        pk.x = *(unsigned*)&h01; pk.y = *(unsigned*)&h23;
        ((uint2*)out)[(size_t)d * 32 + lane] = pk;
    }
}

// ---------------- host side ----------------
static cudaStream_t s_csr = nullptr;
static cudaEvent_t  ev_fork = nullptr, ev_join = nullptr;

extern "C" void kernel_launch(void* const* d_in, const int* in_sizes, int n_in,
                              void* d_out, int out_size) {
    const float* x      = (const float*)d_in[0];
    const void*  ei     = d_in[1];
    const float* W_in   = (const float*)d_in[2];
    const float* as_in  = (const float*)d_in[3];
    const float* ad_in  = (const float*)d_in[4];
    const float* b_in   = (const float*)d_in[5];
    const float* W_h    = (const float*)d_in[6];
    const float* as_h   = (const float*)d_in[7];
    const float* ad_h   = (const float*)d_in[8];
    const float* b_h    = (const float*)d_in[9];
    const float* W_out  = (const float*)d_in[10];
    const float* as_out = (const float*)d_in[11];
    const float* ad_out = (const float*)d_in[12];
    const float* b_out  = (const float*)d_in[13];
    float* out = (float*)d_out;

    __half* p_h16 = nullptr;
    __half* p_x16 = nullptr;
    cudaGetSymbolAddress((void**)&p_h16, g_h16);
    cudaGetSymbolAddress((void**)&p_x16, g_x16);

    if (!s_csr) {
        cudaStreamCreate(&s_csr);
        cudaEventCreateWithFlags(&ev_fork, cudaEventDisableTiming);
        cudaEventCreateWithFlags(&ev_join, cudaEventDisableTiming);
        cudaFuncSetAttribute(k_gemm_wmma_fused<float>,
                             cudaFuncAttributeMaxDynamicSharedMemorySize, GEMM_SMEM);
        cudaFuncSetAttribute(k_gemm_wmma_fused<__half>,
                             cudaFuncAttributeMaxDynamicSharedMemorySize, GEMM_SMEM);
    }

    const int eb2 = (N_EDGES / 2 + 255) / 256;
    const int nb  = (N_NODES + 255) / 256;
    const int gemm_blocks = (N_NODES + 127) / 128;
    const int warp_blocks = (N_NODES * 32 + 255) / 256;

    // ---- fork: CSR build on side stream, layer-0 GEMM in parallel ----
    cudaEventRecord(ev_fork, 0);
    cudaStreamWaitEvent(s_csr, ev_fork, 0);
    k_init_detect<<<nb, 256, 0, s_csr>>>((const long long*)ei);
    k_hist<<<eb2, 256, 0, s_csr>>>(ei);
    k_scan1<<<SCAN_NBLK, SCAN_BLK, 0, s_csr>>>();
    k_scan3_selfloop<<<SCAN_NBLK, SCAN_BLK, 0, s_csr>>>();
    k_scatter<<<eb2, 256, 0, s_csr>>>(ei);
    cudaEventRecord(ev_join, s_csr);

    k_gemm_wmma_fused<float><<<gemm_blocks, 256, GEMM_SMEM>>>(
        x, W_in, p_h16, as_in, ad_in, N_NODES);

    cudaStreamWaitEvent(0, ev_join, 0);
    k_agg<__half><<<warp_blocks, 256>>>(b_in, p_x16, 1);

    k_gemm_wmma_fused<__half><<<gemm_blocks, 256, GEMM_SMEM>>>(
        p_x16, W_h, p_h16, as_h, ad_h, N_NODES);
    k_agg<__half><<<warp_blocks, 256>>>(b_h, p_x16, 1);

    k_gemm_wmma_fused<__half><<<gemm_blocks, 256, GEMM_SMEM>>>(
        p_x16, W_h + 128 * 128, p_h16, as_h + 128, ad_h + 128, N_NODES);
    k_agg<__half><<<warp_blocks, 256>>>(b_h + 128, p_x16, 1);

    k_gemm_wmma_fused<__half><<<gemm_blocks, 256, GEMM_SMEM>>>(
        p_x16, W_out, p_h16, as_out, ad_out, N_NODES);
    k_agg<float><<<warp_blocks, 256>>>(b_out, out, 0);
}